// round 15
// baseline (speedup 1.0000x reference)
#include <cuda_runtime.h>
#include <cuda_fp16.h>
#include <cstdint>

#define NTH 512

// Fragment-major fp16 weights in device scratch (uint4 = one lane's B fragment pair).
// W1F: (((h*16+ic)*16+ks)*4+ntp)*32 + lane
// W2F: (((h*16+ic)*4+ks)*16+ntp)*32 + lane
__device__ uint4 W1F[16*16*16*4*32];
__device__ uint4 W2F[16*16*4*16*32];

__device__ __forceinline__ uint32_t packh2(float a, float b) {
    __half2 h = __floats2half2_rn(a, b);
    return *reinterpret_cast<uint32_t*>(&h);
}
// fast silu: MUFU-based exp + fast divide (err ~2^-21, invisible under fp16 rounding)
__device__ __forceinline__ float silu(float v) {
    return __fdividef(v, 1.0f + __expf(-v));
}

// ---------------- merged weight prep kernel ----------------
__global__ void prep_w(const float* __restrict__ w1, const float* __restrict__ w2) {
    __shared__ float tile[16 * 257];
    int tid = threadIdx.x;
    if (blockIdx.x < 2048) {
        int b = blockIdx.x;
        int kh = b & 7, ic = (b >> 3) & 15, h = b >> 7;
        const float* src = w1 + ((size_t)h * 256 + kh * 32) * 1024 + ic * 64;
        #pragma unroll
        for (int j = 0; j < 2; j++) {
            int flat = tid + j * 256;
            int r = flat >> 4, c4 = flat & 15;
            float4 v = *(const float4*)(src + (size_t)r * 1024 + c4 * 4);
            tile[r*65 + c4*4+0] = v.x; tile[r*65 + c4*4+1] = v.y;
            tile[r*65 + c4*4+2] = v.z; tile[r*65 + c4*4+3] = v.w;
        }
        __syncthreads();
        int lane = tid & 31, ntp = (tid >> 5) & 3, kso = tid >> 7;
        int gcol = lane >> 2, tg = lane & 3;
        int kb = kso * 16 + 2 * tg;
        int n  = ntp * 16 + gcol;
        uint4 o;
        o.x = packh2(tile[kb*65 + n],       tile[(kb+1)*65 + n]);
        o.y = packh2(tile[(kb+8)*65 + n],   tile[(kb+9)*65 + n]);
        o.z = packh2(tile[kb*65 + n+8],     tile[(kb+1)*65 + n+8]);
        o.w = packh2(tile[(kb+8)*65 + n+8], tile[(kb+9)*65 + n+8]);
        int ks = kh * 2 + kso;
        W1F[(((h*16 + ic)*16 + ks)*4 + ntp)*32 + lane] = o;
    } else {
        int b = blockIdx.x - 2048;
        int ks = b & 3, ic = (b >> 2) & 15, h = b >> 6;
        const float* src = w2 + ((size_t)h * 1024 + ic * 64 + ks * 16) * 256;
        #pragma unroll
        for (int j = 0; j < 4; j++) {
            int flat = tid + j * 256;
            int r = flat >> 6, c4 = flat & 63;
            float4 v = *(const float4*)(src + (size_t)r * 256 + c4 * 4);
            tile[r*257 + c4*4+0] = v.x; tile[r*257 + c4*4+1] = v.y;
            tile[r*257 + c4*4+2] = v.z; tile[r*257 + c4*4+3] = v.w;
        }
        __syncthreads();
        #pragma unroll
        for (int j = 0; j < 2; j++) {
            int idx = tid + j * 256;
            int lane = idx & 31, ntp = idx >> 5;
            int gcol = lane >> 2, tg = lane & 3;
            int kb = 2 * tg, n = ntp * 16 + gcol;
            uint4 o;
            o.x = packh2(tile[kb*257 + n],       tile[(kb+1)*257 + n]);
            o.y = packh2(tile[(kb+8)*257 + n],   tile[(kb+9)*257 + n]);
            o.z = packh2(tile[kb*257 + n+8],     tile[(kb+1)*257 + n+8]);
            o.w = packh2(tile[(kb+8)*257 + n+8], tile[(kb+9)*257 + n+8]);
            W2F[(((h*16 + ic)*4 + ks)*16 + ntp)*32 + lane] = o;
        }
    }
}

// ---------------- main fused kernel ----------------
// SMEM (u32 offsets): XA 64KB; HA0/HA1 16KB each. 96KB total.
#define XA  0
#define HA0 16384
#define HA1 20480
#define SMEM_BYTES (24576 * 4)

// group barrier: 4 warps sharing the same wm (contiguous 128 threads), ids 1..4
#define GROUP_BAR(wm) asm volatile("bar.sync %0, %1;" :: "r"((wm) + 1), "r"(128) : "memory")

// f32-accumulate MMA (GEMM1)
__device__ __forceinline__ void mma16816(float* c, uint4 A, uint32_t b0, uint32_t b1) {
    asm volatile("mma.sync.aligned.m16n8k16.row.col.f32.f16.f16.f32 "
        "{%0,%1,%2,%3},{%4,%5,%6,%7},{%8,%9},{%0,%1,%2,%3};"
        : "+f"(c[0]), "+f"(c[1]), "+f"(c[2]), "+f"(c[3])
        : "r"(A.x), "r"(A.y), "r"(A.z), "r"(A.w), "r"(b0), "r"(b1));
}

// fp16-accumulate MMA (GEMM2, flushed to f32 every ic = k64)
__device__ __forceinline__ void mma16816h(uint32_t* c, uint4 A, uint32_t b0, uint32_t b1) {
    asm volatile("mma.sync.aligned.m16n8k16.row.col.f16.f16.f16.f16 "
        "{%0,%1},{%2,%3,%4,%5},{%6,%7},{%0,%1};"
        : "+r"(c[0]), "+r"(c[1])
        : "r"(A.x), "r"(A.y), "r"(A.z), "r"(A.w), "r"(b0), "r"(b1));
}

__global__ __launch_bounds__(NTH, 1)
void mlp_fp16_main(const float* __restrict__ x, float* __restrict__ out) {
    extern __shared__ uint32_t sm[];
    const int tid  = threadIdx.x;
    const int lane = tid & 31, wid = tid >> 5;
    const int g = lane >> 2, tg = lane & 3;
    const int wm = wid >> 2, wn = wid & 3;
    const int head = blockIdx.y;
    const int n0 = blockIdx.x * 128;

    // ---- stage x[128x256] -> fp16 A-fragment-major ----
    {
        const float* xb = x + ((size_t)head * 8192 + n0) * 256;
        #pragma unroll
        for (int j = 0; j < 16; j++) {
            int idx = tid + j * NTH;
            int m = idx >> 6, c4 = idx & 63;
            float4 v = *(const float4*)(xb + (size_t)m * 256 + c4 * 4);
            int ks  = c4 >> 2;
            int hi  = (c4 >> 1) & 1;
            int tg0 = (c4 & 1) * 2;
            int mt = m >> 4, gg = m & 7, mhi = (m >> 3) & 1;
            int reg = hi * 2 + mhi;
            int base = XA + ((ks * 8 + mt) * 32 + gg * 4) * 4 + reg;
            sm[base + tg0 * 4]       = packh2(v.x, v.y);
            sm[base + (tg0 + 1) * 4] = packh2(v.z, v.w);
        }
    }
    __syncthreads();   // only block-wide barrier (x tile is read-only afterwards)

    float acc2[2][8][4];
    #pragma unroll
    for (int mt = 0; mt < 2; mt++)
        #pragma unroll
        for (int nt = 0; nt < 8; nt++)
            #pragma unroll
            for (int r = 0; r < 4; r++) acc2[mt][nt][r] = 0.0f;

    const uint4* w1base0 = W1F + (size_t)(head * 16) * 2048 + wn * 32 + lane;
    const uint4* w2base0 = W2F + (size_t)(head * 16) * 2048 + wn * 4 * 32 + lane;

    #pragma unroll 1
    for (int ic = 0; ic < 16; ic++) {
        const uint4* bp = w1base0 + (size_t)ic * 2048;
        const uint4* bq = w2base0 + (size_t)ic * 2048;
        uint32_t* haw = sm + ((ic & 1) ? HA1 : HA0);

        // ===== GEMM1: z[128x64] = x[128x256] @ w1 chunk (f32 accum, A+B pipelined) =====
        float acc1[2][2][4];
        #pragma unroll
        for (int mt = 0; mt < 2; mt++)
            #pragma unroll
            for (int np = 0; np < 2; np++)
                #pragma unroll
                for (int r = 0; r < 4; r++) acc1[mt][np][r] = 0.0f;

        uint4 B0  = bp[0];
        uint4 B1  = bp[128];
        uint4 A0c = *(const uint4*)(sm + XA + ((wm * 2) * 32 + lane) * 4);
        uint4 A1c = *(const uint4*)(sm + XA + ((wm * 2 + 1) * 32 + lane) * 4);
        #pragma unroll
        for (int ks = 0; ks < 16; ks++) {
            uint4 B2, A0n, A1n;
            if (ks < 14) B2 = bp[(ks + 2) * 128];
            if (ks < 15) {
                A0n = *(const uint4*)(sm + XA + (((ks + 1) * 8 + wm * 2) * 32 + lane) * 4);
                A1n = *(const uint4*)(sm + XA + (((ks + 1) * 8 + wm * 2 + 1) * 32 + lane) * 4);
            }
            mma16816(acc1[0][0], A0c, B0.x, B0.y);
            mma16816(acc1[0][1], A0c, B0.z, B0.w);
            mma16816(acc1[1][0], A1c, B0.x, B0.y);
            mma16816(acc1[1][1], A1c, B0.z, B0.w);
            B0 = B1; B1 = B2; A0c = A0n; A1c = A1n;
        }

        // prefetch GEMM2 ks=0 B fragments FIRST (in flight across silu + barrier)
        uint4 C0 = bq[0];
        uint4 C1 = bq[32];

        // ---- silu -> h A-fragments (group-visible buffer) ----
        #pragma unroll
        for (int mt = 0; mt < 2; mt++)
            #pragma unroll
            for (int np = 0; np < 2; np++) {
                uint2 hv;
                hv.x = packh2(silu(acc1[mt][np][0]), silu(acc1[mt][np][1]));
                hv.y = packh2(silu(acc1[mt][np][2]), silu(acc1[mt][np][3]));
                *(uint2*)(haw + ((wn * 8 + wm * 2 + mt) * 32 + lane) * 4 + np * 2) = hv;
            }

        GROUP_BAR(wm);   // only the 4 same-wm warps need to rendezvous

        // ===== GEMM2: fp16 accumulators over k=64, flushed to f32 after the loop =====
        uint32_t acc2h[2][8][2];
        #pragma unroll
        for (int mt = 0; mt < 2; mt++)
            #pragma unroll
            for (int nt = 0; nt < 8; nt++) {
                acc2h[mt][nt][0] = 0u;
                acc2h[mt][nt][1] = 0u;
            }

        uint4 A0g = *(const uint4*)(haw + ((wm * 2) * 32 + lane) * 4);
        uint4 A1g = *(const uint4*)(haw + ((wm * 2 + 1) * 32 + lane) * 4);
        #pragma unroll
        for (int ks = 0; ks < 4; ks++) {
            uint4 C2 = bq[ks * 512 + 64];
            uint4 C3 = bq[ks * 512 + 96];
            uint4 D0, D1, A0n, A1n;
            if (ks < 3) {
                D0 = bq[(ks + 1) * 512];
                D1 = bq[(ks + 1) * 512 + 32];
                A0n = *(const uint4*)(haw + (((ks + 1) * 8 + wm * 2) * 32 + lane) * 4);
                A1n = *(const uint4*)(haw + (((ks + 1) * 8 + wm * 2 + 1) * 32 + lane) * 4);
            }
            mma16816h(acc2h[0][0], A0g, C0.x, C0.y);
            mma16816h(acc2h[0][1], A0g, C0.z, C0.w);
            mma16816h(acc2h[1][0], A1g, C0.x, C0.y);
            mma16816h(acc2h[1][1], A1g, C0.z, C0.w);
            mma16816h(acc2h[0][2], A0g, C1.x, C1.y);
            mma16816h(acc2h[0][3], A0g, C1.z, C1.w);
            mma16816h(acc2h[1][2], A1g, C1.x, C1.y);
            mma16816h(acc2h[1][3], A1g, C1.z, C1.w);
            mma16816h(acc2h[0][4], A0g, C2.x, C2.y);
            mma16816h(acc2h[0][5], A0g, C2.z, C2.w);
            mma16816h(acc2h[1][4], A1g, C2.x, C2.y);
            mma16816h(acc2h[1][5], A1g, C2.z, C2.w);
            mma16816h(acc2h[0][6], A0g, C3.x, C3.y);
            mma16816h(acc2h[0][7], A0g, C3.z, C3.w);
            mma16816h(acc2h[1][6], A1g, C3.x, C3.y);
            mma16816h(acc2h[1][7], A1g, C3.z, C3.w);
            C0 = D0; C1 = D1; A0g = A0n; A1g = A1n;
        }

        // ---- flush fp16 chunk accumulators into persistent f32 ----
        #pragma unroll
        for (int mt = 0; mt < 2; mt++)
            #pragma unroll
            for (int nt = 0; nt < 8; nt++) {
                float2 lo = __half22float2(*(__half2*)&acc2h[mt][nt][0]);
                float2 hi = __half22float2(*(__half2*)&acc2h[mt][nt][1]);
                acc2[mt][nt][0] += lo.x;
                acc2[mt][nt][1] += lo.y;
                acc2[mt][nt][2] += hi.x;
                acc2[mt][nt][3] += hi.y;
            }
    }

    // ---- epilogue: acc2 -> out (f32) ----
    {
        float* ob = out + ((size_t)head * 8192 + n0 + wm * 32 + g) * 256 + wn * 64 + 2 * tg;
        #pragma unroll
        for (int mt = 0; mt < 2; mt++)
            #pragma unroll
            for (int nt = 0; nt < 8; nt++) {
                *(float2*)(ob + (size_t)(mt * 16) * 256 + nt * 8) =
                    make_float2(acc2[mt][nt][0], acc2[mt][nt][1]);
                *(float2*)(ob + (size_t)(mt * 16 + 8) * 256 + nt * 8) =
                    make_float2(acc2[mt][nt][2], acc2[mt][nt][3]);
            }
    }
}

extern "C" void kernel_launch(void* const* d_in, const int* in_sizes, int n_in,
                              void* d_out, int out_size) {
    const float* x  = (const float*)d_in[0];
    const float* w1 = (const float*)d_in[1];
    const float* w2 = (const float*)d_in[2];
    float* out = (float*)d_out;

    prep_w<<<3072, 256>>>(w1, w2);

    cudaFuncSetAttribute(mlp_fp16_main,
                         cudaFuncAttributeMaxDynamicSharedMemorySize, SMEM_BYTES);
    dim3 grid(8192 / 128, 16);
    mlp_fp16_main<<<grid, NTH, SMEM_BYTES>>>(x, out);
}

// round 16
// speedup vs baseline: 1.1538x; 1.1538x over previous
#include <cuda_runtime.h>
#include <cuda_fp16.h>
#include <cstdint>

#define NTH 512

// Fragment-major fp16 weights in device scratch (uint4 = one lane's B fragment pair).
// W1F: (((h*16+ic)*16+ks)*4+ntp)*32 + lane
// W2F: (((h*16+ic)*4+ks)*16+ntp)*32 + lane
__device__ uint4 W1F[16*16*16*4*32];
__device__ uint4 W2F[16*16*4*16*32];

__device__ __forceinline__ uint32_t packh2(float a, float b) {
    __half2 h = __floats2half2_rn(a, b);
    return *reinterpret_cast<uint32_t*>(&h);
}
// fast silu: MUFU-based exp + fast divide (err ~2^-21, invisible under fp16 rounding)
__device__ __forceinline__ float silu(float v) {
    return __fdividef(v, 1.0f + __expf(-v));
}

// ---------------- merged weight prep kernel ----------------
__global__ void prep_w(const float* __restrict__ w1, const float* __restrict__ w2) {
    __shared__ float tile[16 * 257];
    int tid = threadIdx.x;
    if (blockIdx.x < 2048) {
        int b = blockIdx.x;
        int kh = b & 7, ic = (b >> 3) & 15, h = b >> 7;
        const float* src = w1 + ((size_t)h * 256 + kh * 32) * 1024 + ic * 64;
        #pragma unroll
        for (int j = 0; j < 2; j++) {
            int flat = tid + j * 256;
            int r = flat >> 4, c4 = flat & 15;
            float4 v = *(const float4*)(src + (size_t)r * 1024 + c4 * 4);
            tile[r*65 + c4*4+0] = v.x; tile[r*65 + c4*4+1] = v.y;
            tile[r*65 + c4*4+2] = v.z; tile[r*65 + c4*4+3] = v.w;
        }
        __syncthreads();
        int lane = tid & 31, ntp = (tid >> 5) & 3, kso = tid >> 7;
        int gcol = lane >> 2, tg = lane & 3;
        int kb = kso * 16 + 2 * tg;
        int n  = ntp * 16 + gcol;
        uint4 o;
        o.x = packh2(tile[kb*65 + n],       tile[(kb+1)*65 + n]);
        o.y = packh2(tile[(kb+8)*65 + n],   tile[(kb+9)*65 + n]);
        o.z = packh2(tile[kb*65 + n+8],     tile[(kb+1)*65 + n+8]);
        o.w = packh2(tile[(kb+8)*65 + n+8], tile[(kb+9)*65 + n+8]);
        int ks = kh * 2 + kso;
        W1F[(((h*16 + ic)*16 + ks)*4 + ntp)*32 + lane] = o;
    } else {
        int b = blockIdx.x - 2048;
        int ks = b & 3, ic = (b >> 2) & 15, h = b >> 6;
        const float* src = w2 + ((size_t)h * 1024 + ic * 64 + ks * 16) * 256;
        #pragma unroll
        for (int j = 0; j < 4; j++) {
            int flat = tid + j * 256;
            int r = flat >> 6, c4 = flat & 63;
            float4 v = *(const float4*)(src + (size_t)r * 256 + c4 * 4);
            tile[r*257 + c4*4+0] = v.x; tile[r*257 + c4*4+1] = v.y;
            tile[r*257 + c4*4+2] = v.z; tile[r*257 + c4*4+3] = v.w;
        }
        __syncthreads();
        #pragma unroll
        for (int j = 0; j < 2; j++) {
            int idx = tid + j * 256;
            int lane = idx & 31, ntp = idx >> 5;
            int gcol = lane >> 2, tg = lane & 3;
            int kb = 2 * tg, n = ntp * 16 + gcol;
            uint4 o;
            o.x = packh2(tile[kb*257 + n],       tile[(kb+1)*257 + n]);
            o.y = packh2(tile[(kb+8)*257 + n],   tile[(kb+9)*257 + n]);
            o.z = packh2(tile[kb*257 + n+8],     tile[(kb+1)*257 + n+8]);
            o.w = packh2(tile[(kb+8)*257 + n+8], tile[(kb+9)*257 + n+8]);
            W2F[(((h*16 + ic)*4 + ks)*16 + ntp)*32 + lane] = o;
        }
    }
}

// ---------------- main fused kernel ----------------
// SMEM (u32 offsets): XA 64KB; HA0/HA1 16KB each. 96KB total.
#define XA  0
#define HA0 16384
#define HA1 20480
#define SMEM_BYTES (24576 * 4)

// group barriers (4 warps sharing wm = 128 contiguous threads)
#define BAR_W(wm) asm volatile("bar.sync %0, %1;" :: "r"((wm) + 1), "r"(128) : "memory")
#define BAR_P(wm) asm volatile("bar.sync %0, %1;" :: "r"((wm) + 5), "r"(128) : "memory")

__device__ __forceinline__ void mma16816(float* c, uint4 A, uint32_t b0, uint32_t b1) {
    asm volatile("mma.sync.aligned.m16n8k16.row.col.f32.f16.f16.f32 "
        "{%0,%1,%2,%3},{%4,%5,%6,%7},{%8,%9},{%0,%1,%2,%3};"
        : "+f"(c[0]), "+f"(c[1]), "+f"(c[2]), "+f"(c[3])
        : "r"(A.x), "r"(A.y), "r"(A.z), "r"(A.w), "r"(b0), "r"(b1));
}

__device__ __forceinline__ void store_silu(const float (&a)[2][2][4],
        uint32_t* haw, int wm, int wn, int lane) {
    #pragma unroll
    for (int mt = 0; mt < 2; mt++)
        #pragma unroll
        for (int np = 0; np < 2; np++) {
            uint2 hv;
            hv.x = packh2(silu(a[mt][np][0]), silu(a[mt][np][1]));
            hv.y = packh2(silu(a[mt][np][2]), silu(a[mt][np][3]));
            *(uint2*)(haw + ((wn * 8 + wm * 2 + mt) * 32 + lane) * 4 + np * 2) = hv;
        }
}

// GEMM2 for one ic: acc2 += h[128x64] @ w2 chunk (R12 form, C0..C3 passed in hot)
__device__ __forceinline__ void gemm2_ic(float (&acc2)[2][8][4],
        const uint32_t* ha, const uint4* bq,
        uint4 C0, uint4 C1, uint4 C2, uint4 C3, int wm, int lane) {
    #pragma unroll
    for (int ks = 0; ks < 4; ks++) {
        uint4 D0, D1, D2, D3;
        if (ks < 3) {
            D0 = bq[(ks + 1) * 512];
            D1 = bq[(ks + 1) * 512 + 32];
            D2 = bq[(ks + 1) * 512 + 64];
            D3 = bq[(ks + 1) * 512 + 96];
        }
        uint4 A0 = *(const uint4*)(ha + ((ks * 8 + wm * 2) * 32 + lane) * 4);
        uint4 A1 = *(const uint4*)(ha + ((ks * 8 + wm * 2 + 1) * 32 + lane) * 4);
        mma16816(acc2[0][0], A0, C0.x, C0.y);
        mma16816(acc2[0][1], A0, C0.z, C0.w);
        mma16816(acc2[1][0], A1, C0.x, C0.y);
        mma16816(acc2[1][1], A1, C0.z, C0.w);
        mma16816(acc2[0][2], A0, C1.x, C1.y);
        mma16816(acc2[0][3], A0, C1.z, C1.w);
        mma16816(acc2[1][2], A1, C1.x, C1.y);
        mma16816(acc2[1][3], A1, C1.z, C1.w);
        mma16816(acc2[0][4], A0, C2.x, C2.y);
        mma16816(acc2[0][5], A0, C2.z, C2.w);
        mma16816(acc2[1][4], A1, C2.x, C2.y);
        mma16816(acc2[1][5], A1, C2.z, C2.w);
        mma16816(acc2[0][6], A0, C3.x, C3.y);
        mma16816(acc2[0][7], A0, C3.z, C3.w);
        mma16816(acc2[1][6], A1, C3.x, C3.y);
        mma16816(acc2[1][7], A1, C3.z, C3.w);
        C0 = D0; C1 = D1; C2 = D2; C3 = D3;
    }
}

__global__ __launch_bounds__(NTH, 1)
void mlp_fp16_main(const float* __restrict__ x, float* __restrict__ out) {
    extern __shared__ uint32_t sm[];
    const int tid  = threadIdx.x;
    const int lane = tid & 31, wid = tid >> 5;
    const int g = lane >> 2, tg = lane & 3;
    const int wm = wid >> 2, wn = wid & 3;
    const int head = blockIdx.y;
    const int n0 = blockIdx.x * 128;

    // ---- stage x[128x256] -> fp16 A-fragment-major ----
    {
        const float* xb = x + ((size_t)head * 8192 + n0) * 256;
        #pragma unroll
        for (int j = 0; j < 16; j++) {
            int idx = tid + j * NTH;
            int m = idx >> 6, c4 = idx & 63;
            float4 v = *(const float4*)(xb + (size_t)m * 256 + c4 * 4);
            int ks  = c4 >> 2;
            int hi  = (c4 >> 1) & 1;
            int tg0 = (c4 & 1) * 2;
            int mt = m >> 4, gg = m & 7, mhi = (m >> 3) & 1;
            int reg = hi * 2 + mhi;
            int base = XA + ((ks * 8 + mt) * 32 + gg * 4) * 4 + reg;
            sm[base + tg0 * 4]       = packh2(v.x, v.y);
            sm[base + (tg0 + 1) * 4] = packh2(v.z, v.w);
        }
    }
    __syncthreads();   // only block-wide barrier (x tile is read-only afterwards)

    float acc2[2][8][4];
    #pragma unroll
    for (int mt = 0; mt < 2; mt++)
        #pragma unroll
        for (int nt = 0; nt < 8; nt++)
            #pragma unroll
            for (int r = 0; r < 4; r++) acc2[mt][nt][r] = 0.0f;

    const uint4* w1base0 = W1F + (size_t)(head * 16) * 2048 + wn * 32 + lane;
    const uint4* w2base0 = W2F + (size_t)(head * 16) * 2048 + wn * 4 * 32 + lane;

    #pragma unroll 1
    for (int sic = 0; sic < 8; sic++) {
        const uint4* bpa = w1base0 + (size_t)(2 * sic) * 2048;
        const uint4* bpb = bpa + 2048;
        const uint4* bq0 = w2base0 + (size_t)(2 * sic) * 2048;
        const uint4* bq1 = bq0 + 2048;

        // ===== dual GEMM1: z(ic0) and z(ic1) share every A-fragment load =====
        float acc1a[2][2][4], acc1b[2][2][4];
        #pragma unroll
        for (int mt = 0; mt < 2; mt++)
            #pragma unroll
            for (int np = 0; np < 2; np++)
                #pragma unroll
                for (int r = 0; r < 4; r++) { acc1a[mt][np][r] = 0.0f; acc1b[mt][np][r] = 0.0f; }

        uint4 Ba0 = bpa[0];
        uint4 Ba1 = bpa[128];
        uint4 Bb0 = bpb[0];
        #pragma unroll
        for (int ks = 0; ks < 16; ks++) {
            uint4 Ba2, Bb1;
            if (ks < 14) Ba2 = bpa[(ks + 2) * 128];
            if (ks < 15) Bb1 = bpb[(ks + 1) * 128];
            uint4 A0 = *(const uint4*)(sm + XA + ((ks * 8 + wm * 2) * 32 + lane) * 4);
            uint4 A1 = *(const uint4*)(sm + XA + ((ks * 8 + wm * 2 + 1) * 32 + lane) * 4);
            mma16816(acc1a[0][0], A0, Ba0.x, Ba0.y);
            mma16816(acc1a[0][1], A0, Ba0.z, Ba0.w);
            mma16816(acc1a[1][0], A1, Ba0.x, Ba0.y);
            mma16816(acc1a[1][1], A1, Ba0.z, Ba0.w);
            mma16816(acc1b[0][0], A0, Bb0.x, Bb0.y);
            mma16816(acc1b[0][1], A0, Bb0.z, Bb0.w);
            mma16816(acc1b[1][0], A1, Bb0.x, Bb0.y);
            mma16816(acc1b[1][1], A1, Bb0.z, Bb0.w);
            Ba0 = Ba1; Ba1 = Ba2; Bb0 = Bb1;
        }

        if (sic > 0) BAR_W(wm);   // group-mates finished reading HA0/HA1 of prev super-ic

        // ---- silu both chunks -> HA0 / HA1 ----
        store_silu(acc1a, sm + HA0, wm, wn, lane);
        store_silu(acc1b, sm + HA1, wm, wn, lane);

        // prefetch GEMM2(ic0) B fragments while group converges
        uint4 C0 = bq0[0];
        uint4 C1 = bq0[32];
        uint4 C2 = bq0[64];
        uint4 C3 = bq0[96];

        BAR_P(wm);   // publish HA0/HA1 to the wm group

        // ===== GEMM2 for ic0 then ic1 =====
        gemm2_ic(acc2, sm + HA0, bq0, C0, C1, C2, C3, wm, lane);
        gemm2_ic(acc2, sm + HA1, bq1, bq1[0], bq1[32], bq1[64], bq1[96], wm, lane);
    }

    // ---- epilogue: acc2 -> out (f32) ----
    {
        float* ob = out + ((size_t)head * 8192 + n0 + wm * 32 + g) * 256 + wn * 64 + 2 * tg;
        #pragma unroll
        for (int mt = 0; mt < 2; mt++)
            #pragma unroll
            for (int nt = 0; nt < 8; nt++) {
                *(float2*)(ob + (size_t)(mt * 16) * 256 + nt * 8) =
                    make_float2(acc2[mt][nt][0], acc2[mt][nt][1]);
                *(float2*)(ob + (size_t)(mt * 16 + 8) * 256 + nt * 8) =
                    make_float2(acc2[mt][nt][2], acc2[mt][nt][3]);
            }
    }
}

extern "C" void kernel_launch(void* const* d_in, const int* in_sizes, int n_in,
                              void* d_out, int out_size) {
    const float* x  = (const float*)d_in[0];
    const float* w1 = (const float*)d_in[1];
    const float* w2 = (const float*)d_in[2];
    float* out = (float*)d_out;

    prep_w<<<3072, 256>>>(w1, w2);

    cudaFuncSetAttribute(mlp_fp16_main,
                         cudaFuncAttributeMaxDynamicSharedMemorySize, SMEM_BYTES);
    dim3 grid(8192 / 128, 16);
    mlp_fp16_main<<<grid, NTH, SMEM_BYTES>>>(x, out);
}

// round 17
// speedup vs baseline: 1.2861x; 1.1147x over previous
#include <cuda_runtime.h>
#include <cuda_fp16.h>
#include <cstdint>

#define NTH 256

// Fragment-major fp16 weights in device scratch (uint4 = one lane's B fragment pair).
// W1F: (((h*16+ic)*16+ks)*4+ntp)*32 + lane
// W2F: (((h*16+ic)*4+ks)*16+ntp)*32 + lane
__device__ uint4 W1F[16*16*16*4*32];
__device__ uint4 W2F[16*16*4*16*32];

__device__ __forceinline__ uint32_t packh2(float a, float b) {
    __half2 h = __floats2half2_rn(a, b);
    return *reinterpret_cast<uint32_t*>(&h);
}
// fast silu: MUFU-based exp + fast divide (err ~2^-21, invisible under fp16 rounding)
__device__ __forceinline__ float silu(float v) {
    return __fdividef(v, 1.0f + __expf(-v));
}

// ---------------- merged weight prep kernel ----------------
__global__ void prep_w(const float* __restrict__ w1, const float* __restrict__ w2) {
    __shared__ float tile[16 * 257];
    int tid = threadIdx.x;
    if (blockIdx.x < 2048) {
        int b = blockIdx.x;
        int kh = b & 7, ic = (b >> 3) & 15, h = b >> 7;
        const float* src = w1 + ((size_t)h * 256 + kh * 32) * 1024 + ic * 64;
        #pragma unroll
        for (int j = 0; j < 2; j++) {
            int flat = tid + j * 256;
            int r = flat >> 4, c4 = flat & 15;
            float4 v = *(const float4*)(src + (size_t)r * 1024 + c4 * 4);
            tile[r*65 + c4*4+0] = v.x; tile[r*65 + c4*4+1] = v.y;
            tile[r*65 + c4*4+2] = v.z; tile[r*65 + c4*4+3] = v.w;
        }
        __syncthreads();
        int lane = tid & 31, ntp = (tid >> 5) & 3, kso = tid >> 7;
        int gcol = lane >> 2, tg = lane & 3;
        int kb = kso * 16 + 2 * tg;
        int n  = ntp * 16 + gcol;
        uint4 o;
        o.x = packh2(tile[kb*65 + n],       tile[(kb+1)*65 + n]);
        o.y = packh2(tile[(kb+8)*65 + n],   tile[(kb+9)*65 + n]);
        o.z = packh2(tile[kb*65 + n+8],     tile[(kb+1)*65 + n+8]);
        o.w = packh2(tile[(kb+8)*65 + n+8], tile[(kb+9)*65 + n+8]);
        int ks = kh * 2 + kso;
        W1F[(((h*16 + ic)*16 + ks)*4 + ntp)*32 + lane] = o;
    } else {
        int b = blockIdx.x - 2048;
        int ks = b & 3, ic = (b >> 2) & 15, h = b >> 6;
        const float* src = w2 + ((size_t)h * 1024 + ic * 64 + ks * 16) * 256;
        #pragma unroll
        for (int j = 0; j < 4; j++) {
            int flat = tid + j * 256;
            int r = flat >> 6, c4 = flat & 63;
            float4 v = *(const float4*)(src + (size_t)r * 256 + c4 * 4);
            tile[r*257 + c4*4+0] = v.x; tile[r*257 + c4*4+1] = v.y;
            tile[r*257 + c4*4+2] = v.z; tile[r*257 + c4*4+3] = v.w;
        }
        __syncthreads();
        #pragma unroll
        for (int j = 0; j < 2; j++) {
            int idx = tid + j * 256;
            int lane = idx & 31, ntp = idx >> 5;
            int gcol = lane >> 2, tg = lane & 3;
            int kb = 2 * tg, n = ntp * 16 + gcol;
            uint4 o;
            o.x = packh2(tile[kb*257 + n],       tile[(kb+1)*257 + n]);
            o.y = packh2(tile[(kb+8)*257 + n],   tile[(kb+9)*257 + n]);
            o.z = packh2(tile[kb*257 + n+8],     tile[(kb+1)*257 + n+8]);
            o.w = packh2(tile[(kb+8)*257 + n+8], tile[(kb+9)*257 + n+8]);
            W2F[(((h*16 + ic)*4 + ks)*16 + ntp)*32 + lane] = o;
        }
    }
}

// ---------------- main fused kernel (BM=64, 2 CTAs/SM) ----------------
// SMEM (u32 offsets): XA 32KB (16ks x 4mt x 32 x 4); HA0/HA1 8KB each. 48KB/CTA.
#define XA  0
#define HA0 8192
#define HA1 10240
#define SMEM_BYTES (12288 * 4)

// group barriers (4 warps sharing wm = 128 contiguous threads), ids 1..4
#define BAR_W(wm) asm volatile("bar.sync %0, %1;" :: "r"((wm) + 1), "r"(128) : "memory")
#define BAR_P(wm) asm volatile("bar.sync %0, %1;" :: "r"((wm) + 3), "r"(128) : "memory")

__device__ __forceinline__ void mma16816(float* c, uint4 A, uint32_t b0, uint32_t b1) {
    asm volatile("mma.sync.aligned.m16n8k16.row.col.f32.f16.f16.f32 "
        "{%0,%1,%2,%3},{%4,%5,%6,%7},{%8,%9},{%0,%1,%2,%3};"
        : "+f"(c[0]), "+f"(c[1]), "+f"(c[2]), "+f"(c[3])
        : "r"(A.x), "r"(A.y), "r"(A.z), "r"(A.w), "r"(b0), "r"(b1));
}

__device__ __forceinline__ void store_silu(const float (&a)[2][2][4],
        uint32_t* haw, int wm, int wn, int lane) {
    #pragma unroll
    for (int mt = 0; mt < 2; mt++)
        #pragma unroll
        for (int np = 0; np < 2; np++) {
            uint2 hv;
            hv.x = packh2(silu(a[mt][np][0]), silu(a[mt][np][1]));
            hv.y = packh2(silu(a[mt][np][2]), silu(a[mt][np][3]));
            *(uint2*)(haw + ((wn * 4 + wm * 2 + mt) * 32 + lane) * 4 + np * 2) = hv;
        }
}

// GEMM2 for one ic: acc2 += h[64x64] @ w2 chunk
__device__ __forceinline__ void gemm2_ic(float (&acc2)[2][8][4],
        const uint32_t* ha, const uint4* bq,
        uint4 C0, uint4 C1, uint4 C2, uint4 C3, int wm, int lane) {
    #pragma unroll
    for (int ks = 0; ks < 4; ks++) {
        uint4 D0, D1, D2, D3;
        if (ks < 3) {
            D0 = bq[(ks + 1) * 512];
            D1 = bq[(ks + 1) * 512 + 32];
            D2 = bq[(ks + 1) * 512 + 64];
            D3 = bq[(ks + 1) * 512 + 96];
        }
        uint4 A0 = *(const uint4*)(ha + ((ks * 4 + wm * 2) * 32 + lane) * 4);
        uint4 A1 = *(const uint4*)(ha + ((ks * 4 + wm * 2 + 1) * 32 + lane) * 4);
        mma16816(acc2[0][0], A0, C0.x, C0.y);
        mma16816(acc2[0][1], A0, C0.z, C0.w);
        mma16816(acc2[1][0], A1, C0.x, C0.y);
        mma16816(acc2[1][1], A1, C0.z, C0.w);
        mma16816(acc2[0][2], A0, C1.x, C1.y);
        mma16816(acc2[0][3], A0, C1.z, C1.w);
        mma16816(acc2[1][2], A1, C1.x, C1.y);
        mma16816(acc2[1][3], A1, C1.z, C1.w);
        mma16816(acc2[0][4], A0, C2.x, C2.y);
        mma16816(acc2[0][5], A0, C2.z, C2.w);
        mma16816(acc2[1][4], A1, C2.x, C2.y);
        mma16816(acc2[1][5], A1, C2.z, C2.w);
        mma16816(acc2[0][6], A0, C3.x, C3.y);
        mma16816(acc2[0][7], A0, C3.z, C3.w);
        mma16816(acc2[1][6], A1, C3.x, C3.y);
        mma16816(acc2[1][7], A1, C3.z, C3.w);
        C0 = D0; C1 = D1; C2 = D2; C3 = D3;
    }
}

__global__ __launch_bounds__(NTH, 2)
void mlp_fp16_main(const float* __restrict__ x, float* __restrict__ out) {
    extern __shared__ uint32_t sm[];
    const int tid  = threadIdx.x;
    const int lane = tid & 31, wid = tid >> 5;
    const int g = lane >> 2, tg = lane & 3;
    const int wm = wid >> 2, wn = wid & 3;
    const int head = blockIdx.y;
    const int n0 = blockIdx.x * 64;

    // ---- stage x[64x256] -> fp16 A-fragment-major ----
    {
        const float* xb = x + ((size_t)head * 8192 + n0) * 256;
        #pragma unroll
        for (int j = 0; j < 16; j++) {
            int idx = tid + j * NTH;
            int m = idx >> 6, c4 = idx & 63;
            float4 v = *(const float4*)(xb + (size_t)m * 256 + c4 * 4);
            int ks  = c4 >> 2;
            int hi  = (c4 >> 1) & 1;
            int tg0 = (c4 & 1) * 2;
            int mt = m >> 4, gg = m & 7, mhi = (m >> 3) & 1;
            int reg = hi * 2 + mhi;
            int base = XA + ((ks * 4 + mt) * 32 + gg * 4) * 4 + reg;
            sm[base + tg0 * 4]       = packh2(v.x, v.y);
            sm[base + (tg0 + 1) * 4] = packh2(v.z, v.w);
        }
    }
    __syncthreads();   // only block-wide barrier (x tile is read-only afterwards)

    float acc2[2][8][4];
    #pragma unroll
    for (int mt = 0; mt < 2; mt++)
        #pragma unroll
        for (int nt = 0; nt < 8; nt++)
            #pragma unroll
            for (int r = 0; r < 4; r++) acc2[mt][nt][r] = 0.0f;

    const uint4* w1base0 = W1F + (size_t)(head * 16) * 2048 + wn * 32 + lane;
    const uint4* w2base0 = W2F + (size_t)(head * 16) * 2048 + wn * 4 * 32 + lane;

    #pragma unroll 1
    for (int sic = 0; sic < 8; sic++) {
        const uint4* bpa = w1base0 + (size_t)(2 * sic) * 2048;
        const uint4* bpb = bpa + 2048;
        const uint4* bq0 = w2base0 + (size_t)(2 * sic) * 2048;
        const uint4* bq1 = bq0 + 2048;

        // ===== dual GEMM1: z(ic0) and z(ic1) share every A-fragment load =====
        float acc1a[2][2][4], acc1b[2][2][4];
        #pragma unroll
        for (int mt = 0; mt < 2; mt++)
            #pragma unroll
            for (int np = 0; np < 2; np++)
                #pragma unroll
                for (int r = 0; r < 4; r++) { acc1a[mt][np][r] = 0.0f; acc1b[mt][np][r] = 0.0f; }

        uint4 Ba0 = bpa[0];
        uint4 Ba1 = bpa[128];
        uint4 Bb0 = bpb[0];
        #pragma unroll
        for (int ks = 0; ks < 16; ks++) {
            uint4 Ba2, Bb1;
            if (ks < 14) Ba2 = bpa[(ks + 2) * 128];
            if (ks < 15) Bb1 = bpb[(ks + 1) * 128];
            uint4 A0 = *(const uint4*)(sm + XA + ((ks * 4 + wm * 2) * 32 + lane) * 4);
            uint4 A1 = *(const uint4*)(sm + XA + ((ks * 4 + wm * 2 + 1) * 32 + lane) * 4);
            mma16816(acc1a[0][0], A0, Ba0.x, Ba0.y);
            mma16816(acc1a[0][1], A0, Ba0.z, Ba0.w);
            mma16816(acc1a[1][0], A1, Ba0.x, Ba0.y);
            mma16816(acc1a[1][1], A1, Ba0.z, Ba0.w);
            mma16816(acc1b[0][0], A0, Bb0.x, Bb0.y);
            mma16816(acc1b[0][1], A0, Bb0.z, Bb0.w);
            mma16816(acc1b[1][0], A1, Bb0.x, Bb0.y);
            mma16816(acc1b[1][1], A1, Bb0.z, Bb0.w);
            Ba0 = Ba1; Ba1 = Ba2; Bb0 = Bb1;
        }

        if (sic > 0) BAR_W(wm);   // group-mates finished reading HA0/HA1 of prev super-ic

        // ---- silu both chunks -> HA0 / HA1 ----
        store_silu(acc1a, sm + HA0, wm, wn, lane);
        store_silu(acc1b, sm + HA1, wm, wn, lane);

        // prefetch GEMM2(ic0) B fragments while group converges
        uint4 C0 = bq0[0];
        uint4 C1 = bq0[32];
        uint4 C2 = bq0[64];
        uint4 C3 = bq0[96];

        BAR_P(wm);   // publish HA0/HA1 to the wm group

        // ===== GEMM2 for ic0 then ic1 =====
        gemm2_ic(acc2, sm + HA0, bq0, C0, C1, C2, C3, wm, lane);
        gemm2_ic(acc2, sm + HA1, bq1, bq1[0], bq1[32], bq1[64], bq1[96], wm, lane);
    }

    // ---- epilogue: acc2 -> out (f32) ----
    {
        float* ob = out + ((size_t)head * 8192 + n0 + wm * 32 + g) * 256 + wn * 64 + 2 * tg;
        #pragma unroll
        for (int mt = 0; mt < 2; mt++)
            #pragma unroll
            for (int nt = 0; nt < 8; nt++) {
                *(float2*)(ob + (size_t)(mt * 16) * 256 + nt * 8) =
                    make_float2(acc2[mt][nt][0], acc2[mt][nt][1]);
                *(float2*)(ob + (size_t)(mt * 16 + 8) * 256 + nt * 8) =
                    make_float2(acc2[mt][nt][2], acc2[mt][nt][3]);
            }
    }
}

extern "C" void kernel_launch(void* const* d_in, const int* in_sizes, int n_in,
                              void* d_out, int out_size) {
    const float* x  = (const float*)d_in[0];
    const float* w1 = (const float*)d_in[1];
    const float* w2 = (const float*)d_in[2];
    float* out = (float*)d_out;

    prep_w<<<3072, 256>>>(w1, w2);

    cudaFuncSetAttribute(mlp_fp16_main,
                         cudaFuncAttributeMaxDynamicSharedMemorySize, SMEM_BYTES);
    dim3 grid(8192 / 64, 16);
    mlp_fp16_main<<<grid, NTH, SMEM_BYTES>>>(x, out);
}